// round 2
// baseline (speedup 1.0000x reference)
#include <cuda_runtime.h>

// Problem constants
#define N_SAMPLES 65536
#define EMB       1536
#define HALF      768
#define BINS      257
#define PLANE     (BINS * BINS)   // 66049
#define ROW_F4    (EMB / 4)       // 384 float4 per output row
#define HALF_F4   (HALF / 4)      // 192 float4 per half-row (3 KB)
#define MAXB      1536            // per-bucket capacity (expected max ~620, 2.5x margin)
#define SPLITS    8               // CTAs per bucket in the scatter kernel

// Factored 1D table: T[p][e] = pe_value(e,p) + lc[e]. 1.58 MB, L2-resident.
__device__ float          g_table[BINS * EMB];
// Bucket counters: [0..256] = w-side (idx2), [257..513] = h-side (idx1)
__device__ int            g_cnt[2 * BINS];
// Bucket row lists (row ids fit in uint16: 0..65535)
__device__ unsigned short g_list[2 * BINS * MAXB];

// ---------------------------------------------------------------------------
// Kernel A: build factored table from pos_embeddings (bit-exact: pe[e,h,w] is
// separable — e<HALF depends only on w, e>=HALF only on h). Also zeroes the
// bucket counters for this launch.
// ---------------------------------------------------------------------------
__global__ void build_table_kernel(const float* __restrict__ pe,
                                   const float* __restrict__ lc) {
    int idx = blockIdx.x * blockDim.x + threadIdx.x;
    if (idx < 2 * BINS) g_cnt[idx] = 0;
    if (idx >= BINS * EMB) return;
    int p = idx / EMB;
    int e = idx % EMB;
    float v;
    if (e < HALF) {
        v = pe[(size_t)e * PLANE + p];                 // h = 0, w = p
    } else {
        v = pe[(size_t)e * PLANE + (size_t)p * BINS];  // h = p, w = 0
    }
    g_table[idx] = v + lc[e];
}

// ---------------------------------------------------------------------------
// Exact digitize (validated rel_err == 0.0 in R1): positions[k] = -5 + k/25.6,
// all edges exactly representable in fp32; guess + fixup reproduces
// searchsorted(side='right'). Result in [1, 256].
// ---------------------------------------------------------------------------
__device__ __forceinline__ int digitize256(float x) {
    float xc = fminf(fmaxf(x, -5.0f), 5.0f - 1e-6f);
    int k = (int)floorf((xc + 5.0f) * 25.6f);
    k = max(0, min(k, 255));
    while (k < 255 && fmaf((float)(k + 1), 0.0390625f, -5.0f) <= xc) k++;
    while (k > 0   && fmaf((float)k,       0.0390625f, -5.0f) >  xc) k--;
    return k + 1;
}

// ---------------------------------------------------------------------------
// Kernel B: bucketize all rows by (idx2 -> w buckets, idx1 -> h buckets).
// 131072 global atomics spread over 514 addresses — a few microseconds.
// List order is nondeterministic but the final output is order-invariant.
// ---------------------------------------------------------------------------
__global__ void __launch_bounds__(256)
bucketize_kernel(const float* __restrict__ x1, const float* __restrict__ x2) {
    int i = blockIdx.x * blockDim.x + threadIdx.x;
    if (i >= N_SAMPLES) return;
    int i2 = digitize256(x2[i]);                       // w-side, buckets [0..256]
    int s2 = atomicAdd(&g_cnt[i2], 1);
    if (s2 < MAXB) g_list[i2 * MAXB + s2] = (unsigned short)i;
    int i1 = digitize256(x1[i]);                       // h-side, buckets [257..513]
    int s1 = atomicAdd(&g_cnt[BINS + i1], 1);
    if (s1 < MAXB) g_list[(BINS + i1) * MAXB + s1] = (unsigned short)i;
}

// ---------------------------------------------------------------------------
// Kernel C: scatter. CTA = (bucket, split). 192 threads each hold one float4
// of the bucket's 3 KB half-row in a register (table read ONCE per CTA ->
// total L2 read traffic ~13 MB instead of 402 MB), then stream it to every
// output row in the bucket. Writes are fully coalesced 3 KB segments.
// ---------------------------------------------------------------------------
__global__ void __launch_bounds__(192)
scatter_kernel(float4* __restrict__ out) {
    const int bucket = blockIdx.x / SPLITS;            // 0..513
    const int split  = blockIdx.x % SPLITS;
    const int side   = (bucket >= BINS) ? 1 : 0;       // 0 = w half, 1 = h half
    const int bin    = side ? (bucket - BINS) : bucket;

    int cnt = g_cnt[bucket];
    if (cnt > MAXB) cnt = MAXB;

    const float4* __restrict__ tab = reinterpret_cast<const float4*>(g_table);
    const int off = side * HALF_F4 + threadIdx.x;      // float4 offset within row
    const float4 v = tab[(size_t)bin * ROW_F4 + off];  // register-resident payload

    const unsigned short* __restrict__ lst = &g_list[(size_t)bucket * MAXB];

    int r = split;
    // 4-way unrolled main loop for store-MLP
    for (; r + 3 * SPLITS < cnt; r += 4 * SPLITS) {
        int r0 = lst[r];
        int r1 = lst[r + SPLITS];
        int r2 = lst[r + 2 * SPLITS];
        int r3 = lst[r + 3 * SPLITS];
        out[(size_t)r0 * ROW_F4 + off] = v;
        out[(size_t)r1 * ROW_F4 + off] = v;
        out[(size_t)r2 * ROW_F4 + off] = v;
        out[(size_t)r3 * ROW_F4 + off] = v;
    }
    for (; r < cnt; r += SPLITS) {
        int row = lst[r];
        out[(size_t)row * ROW_F4 + off] = v;
    }
}

extern "C" void kernel_launch(void* const* d_in, const int* in_sizes, int n_in,
                              void* d_out, int out_size) {
    const float* x1 = (const float*)d_in[0];
    const float* x2 = (const float*)d_in[1];
    const float* pe = (const float*)d_in[2];
    const float* lc = (const float*)d_in[3];
    float4* out = (float4*)d_out;

    build_table_kernel<<<(BINS * EMB + 255) / 256, 256>>>(pe, lc);
    bucketize_kernel<<<N_SAMPLES / 256, 256>>>(x1, x2);
    scatter_kernel<<<2 * BINS * SPLITS, 192>>>(out);
}

// round 3
// speedup vs baseline: 1.4323x; 1.4323x over previous
#include <cuda_runtime.h>

// Problem constants
#define N_SAMPLES 65536
#define EMB       1536
#define HALF      768        // e<HALF depends only on w (idx2); e>=HALF only on h (idx1)
#define BINS      257
#define PLANE     (BINS * BINS)   // 66049
#define ROW_F4    (EMB / 4)       // 384 float4 per output row
#define HALF_F4   (HALF / 4)      // 192

// Factored 1D table: T[p][e] = pe_value(e,p) + lc[e]. 1.58 MB -> L2 resident.
__device__ float g_table[BINS * EMB];

// ---------------------------------------------------------------------------
// Kernel A: build the factored table. One WARP per embedding dim e.
//   w-side (e < HALF):  lane reads pe[e*PLANE + p], consecutive p -> coalesced
//   h-side (e >= HALF): lane reads pe[e*PLANE + p*BINS], 1028B stride, MLP=9
// Writes g_table[p*EMB + e] are 6KB-strided but target the small L2-resident
// table, where partial sectors merge for free.
// ---------------------------------------------------------------------------
__global__ void __launch_bounds__(256)
build_table_kernel(const float* __restrict__ pe, const float* __restrict__ lc) {
    const int e    = blockIdx.x * 8 + (threadIdx.x >> 5);   // 0..1535
    const int lane = threadIdx.x & 31;
    const float bias = __ldg(&lc[e]);
    const size_t base = (size_t)e * PLANE;

    if (e < HALF) {
        #pragma unroll
        for (int k = 0; k < 9; k++) {
            int p = k * 32 + lane;
            if (p < BINS)
                g_table[(size_t)p * EMB + e] = __ldg(&pe[base + p]) + bias;
        }
    } else {
        #pragma unroll
        for (int k = 0; k < 9; k++) {
            int p = k * 32 + lane;
            if (p < BINS)
                g_table[(size_t)p * EMB + e] = __ldg(&pe[base + (size_t)p * BINS]) + bias;
        }
    }
}

// ---------------------------------------------------------------------------
// Exact digitize (rel_err == 0.0 validated): positions[k] = -5 + k/25.6, all
// edges exactly representable in fp32; guess + fixup reproduces
// searchsorted(side='right'). Result in [1, 256].
// ---------------------------------------------------------------------------
__device__ __forceinline__ int digitize256(float x) {
    float xc = fminf(fmaxf(x, -5.0f), 5.0f - 1e-6f);
    int k = (int)floorf((xc + 5.0f) * 25.6f);
    k = max(0, min(k, 255));
    while (k < 255 && fmaf((float)(k + 1), 0.0390625f, -5.0f) <= xc) k++;
    while (k > 0   && fmaf((float)k,       0.0390625f, -5.0f) >  xc) k--;
    return k + 1;
}

// ---------------------------------------------------------------------------
// Kernel B (proven R1 structure): one warp copies one 6KB output row.
//   out[i, e] = T[(e < 768 ? idx2 : idx1)][e]
// Table reads hit L1 for the hot central bins (~150KB/SM working set);
// output stores use __stcs (streaming, evict-first) to keep L2 for the table.
// Block = 256 threads (8 warps); block owns 32 consecutive rows.
// ---------------------------------------------------------------------------
__global__ void __launch_bounds__(256)
row_copy_kernel(const float* __restrict__ x1,
                const float* __restrict__ x2,
                float4* __restrict__ out) {
    const float4* __restrict__ tab = reinterpret_cast<const float4*>(g_table);
    const int warp = threadIdx.x >> 5;
    const int lane = threadIdx.x & 31;
    const int row0 = blockIdx.x * 32 + warp;

    #pragma unroll
    for (int r = 0; r < 4; r++) {
        const int row = row0 + r * 8;
        const int i1 = digitize256(x1[row]);
        const int i2 = digitize256(x2[row]);
        const float4* __restrict__ srcW = tab + (size_t)i2 * ROW_F4; // e <  768
        const float4* __restrict__ srcH = tab + (size_t)i1 * ROW_F4; // e >= 768
        float4* __restrict__ dst = out + (size_t)row * ROW_F4;

        #pragma unroll
        for (int k = 0; k < 12; k++) {
            const int e4 = k * 32 + lane;                 // 0..383
            const float4 v = (e4 < HALF_F4) ? __ldg(&srcW[e4]) : __ldg(&srcH[e4]);
            __stcs(&dst[e4], v);
        }
    }
}

extern "C" void kernel_launch(void* const* d_in, const int* in_sizes, int n_in,
                              void* d_out, int out_size) {
    const float* x1 = (const float*)d_in[0];
    const float* x2 = (const float*)d_in[1];
    const float* pe = (const float*)d_in[2];
    const float* lc = (const float*)d_in[3];
    float4* out = (float4*)d_out;

    // A: 1536 e-rows, one warp each -> 192 blocks of 8 warps
    build_table_kernel<<<EMB / 8, 256>>>(pe, lc);
    // B: 65536 rows / 32 rows-per-block = 2048 blocks
    row_copy_kernel<<<N_SAMPLES / 32, 256>>>(x1, x2, out);
}